// round 12
// baseline (speedup 1.0000x reference)
#include <cuda_runtime.h>
#include <cuda_bf16.h>
#include <mma.h>
#include <math.h>
#include <stdint.h>

using namespace nvcuda;

// Problem constants (dataset-fixed): C=128, K=32, N=200000, B=16.
#define C_DIM 128
#define K_DIM 32
#define N_MAX 200704
#define ITERS 20

// ---------------- scratch ----------------
__device__ float g_L[(size_t)N_MAX * K_DIM];   // E = exp(L-rowmax) -> final S
__device__ float g_t[ITERS][K_DIM];            // per-iter column sums; t[0] from logits kernel
__device__ unsigned int g_cnt[ITERS];          // per-iter arrival counters (1..19 used)

// split 4 consecutive floats into hi/lo bf16x2 pairs
__device__ __forceinline__ void split4(float a, float b, float c, float d, uint2& hi, uint2& lo) {
    __nv_bfloat162 h0 = __floats2bfloat162_rn(a, b);
    __nv_bfloat162 h1 = __floats2bfloat162_rn(c, d);
    __nv_bfloat162 l0 = __floats2bfloat162_rn(a - __low2float(h0), b - __high2float(h0));
    __nv_bfloat162 l1 = __floats2bfloat162_rn(c - __low2float(h1), d - __high2float(h1));
    hi.x = *reinterpret_cast<uint32_t*>(&h0);
    hi.y = *reinterpret_cast<uint32_t*>(&h1);
    lo.x = *reinterpret_cast<uint32_t*>(&l0);
    lo.y = *reinterpret_cast<uint32_t*>(&l1);
}

// ================= persistent wmma MLP -> E (exp(logits-rowmax)) + iter-0 colsums =================
#define LDA 136
#define LDD 132
#define LDD2 36
#define OF_AHI  0
#define OF_ALO  (OF_AHI + 128 * LDA * 2)
#define OF_W1HI (OF_ALO + 128 * LDA * 2)
#define OF_W1LO (OF_W1HI + 128 * LDA * 2)
#define OF_W2HI (OF_W1LO + 128 * LDA * 2)
#define OF_W2LO (OF_W2HI + 32 * LDA * 2)
#define OF_D    (OF_W2LO + 32 * LDA * 2)
#define OF_B1   (OF_D + 128 * LDD * 4)
#define OF_B2   (OF_B1 + 512)
#define OF_T0   (OF_B2 + 128)
#define SMEM_TC (OF_T0 + 256)

__global__ void __launch_bounds__(512, 1)
k_logits_tc(const float* __restrict__ x, const float* __restrict__ W1,
            const float* __restrict__ b1, const float* __restrict__ W2,
            const float* __restrict__ b2, const float* __restrict__ scaling,
            int N, int ntiles)
{
    extern __shared__ char sm[];
    __nv_bfloat16* Ahi = (__nv_bfloat16*)(sm + OF_AHI);
    __nv_bfloat16* Alo = (__nv_bfloat16*)(sm + OF_ALO);
    __nv_bfloat16* W1h = (__nv_bfloat16*)(sm + OF_W1HI);
    __nv_bfloat16* W1l = (__nv_bfloat16*)(sm + OF_W1LO);
    __nv_bfloat16* W2h = (__nv_bfloat16*)(sm + OF_W2HI);
    __nv_bfloat16* W2l = (__nv_bfloat16*)(sm + OF_W2LO);
    float* D   = (float*)(sm + OF_D);
    float* b1s = (float*)(sm + OF_B1);
    float* b2s = (float*)(sm + OF_B2);
    float* t0a = (float*)(sm + OF_T0);   // per-block iter-0 column sums [32]

    const int tid = threadIdx.x, wid = tid >> 5, lane = tid & 31;
    const float sc = __ldg(scaling);

    for (int f = tid; f < 4096; f += 512) {
        int j = f & 127, k0 = (f >> 7) << 2;
        float v0 = W1[(k0 + 0) * 128 + j], v1 = W1[(k0 + 1) * 128 + j];
        float v2 = W1[(k0 + 2) * 128 + j], v3 = W1[(k0 + 3) * 128 + j];
        uint2 hi, lo; split4(v0, v1, v2, v3, hi, lo);
        *(uint2*)&W1h[j * LDA + k0] = hi;
        *(uint2*)&W1l[j * LDA + k0] = lo;
    }
    for (int f = tid; f < 1024; f += 512) {
        int j = f & 31, k0 = (f >> 5) << 2;
        float v0 = W2[(k0 + 0) * 32 + j], v1 = W2[(k0 + 1) * 32 + j];
        float v2 = W2[(k0 + 2) * 32 + j], v3 = W2[(k0 + 3) * 32 + j];
        uint2 hi, lo; split4(v0, v1, v2, v3, hi, lo);
        *(uint2*)&W2h[j * LDA + k0] = hi;
        *(uint2*)&W2l[j * LDA + k0] = lo;
    }
    if (tid < 128) b1s[tid] = b1[tid];
    else if (tid < 160) b2s[tid - 128] = b2[tid - 128];
    if (tid < 32) t0a[tid] = 0.f;
    __syncthreads();

    for (int t = blockIdx.x; t < ntiles; t += gridDim.x) {
        const int row0 = t << 7;

        // ---- x tile: inline load + split ----
#pragma unroll
        for (int i = 0; i < 8; i++) {
            int f = tid + i * 512;
            int row = f >> 5, c0 = (f & 31) << 2;
            int rr = row0 + row;
            float4 v = (rr < N) ? ((const float4*)x)[(size_t)rr * 32 + (c0 >> 2)]
                                : make_float4(0.f, 0.f, 0.f, 0.f);
            uint2 hi, lo; split4(v.x, v.y, v.z, v.w, hi, lo);
            *(uint2*)&Ahi[row * LDA + c0] = hi;
            *(uint2*)&Alo[row * LDA + c0] = lo;
        }
        __syncthreads();

        // ---- GEMM1 ----
        {
            const int wm = wid >> 2, wn = wid & 3;
            const int m0 = wm * 32, n0 = wn * 32;
            wmma::fragment<wmma::accumulator, 16, 16, 16, float> acc[2][2];
#pragma unroll
            for (int i = 0; i < 2; i++)
#pragma unroll
                for (int j = 0; j < 2; j++) wmma::fill_fragment(acc[i][j], 0.f);
#pragma unroll
            for (int kk = 0; kk < 8; kk++) {
                const int k0 = kk * 16;
                wmma::fragment<wmma::matrix_a, 16, 16, 16, __nv_bfloat16, wmma::row_major> ah[2], al[2];
#pragma unroll
                for (int i = 0; i < 2; i++) {
                    wmma::load_matrix_sync(ah[i], &Ahi[(m0 + i * 16) * LDA + k0], LDA);
                    wmma::load_matrix_sync(al[i], &Alo[(m0 + i * 16) * LDA + k0], LDA);
                }
#pragma unroll
                for (int j = 0; j < 2; j++) {
                    wmma::fragment<wmma::matrix_b, 16, 16, 16, __nv_bfloat16, wmma::col_major> bh, bl;
                    wmma::load_matrix_sync(bh, &W1h[(n0 + j * 16) * LDA + k0], LDA);
                    wmma::load_matrix_sync(bl, &W1l[(n0 + j * 16) * LDA + k0], LDA);
#pragma unroll
                    for (int i = 0; i < 2; i++) {
                        wmma::mma_sync(acc[i][j], ah[i], bh, acc[i][j]);
                        wmma::mma_sync(acc[i][j], ah[i], bl, acc[i][j]);
                        wmma::mma_sync(acc[i][j], al[i], bh, acc[i][j]);
                    }
                }
            }
#pragma unroll
            for (int i = 0; i < 2; i++)
#pragma unroll
                for (int j = 0; j < 2; j++)
                    wmma::store_matrix_sync(&D[(m0 + i * 16) * LDD + n0 + j * 16], acc[i][j],
                                            LDD, wmma::mem_row_major);
        }
        __syncthreads();

        // ---- epilogue1: h = relu(D1+b1) -> re-split into A ----
        {
            const int row = tid >> 2, cb = (tid & 3) * 32;
#pragma unroll
            for (int g = 0; g < 8; g++) {
                int c0 = cb + g * 4;
                float4 d = *(const float4*)&D[row * LDD + c0];
                float h0 = fmaxf(d.x + b1s[c0 + 0], 0.f);
                float h1 = fmaxf(d.y + b1s[c0 + 1], 0.f);
                float h2 = fmaxf(d.z + b1s[c0 + 2], 0.f);
                float h3 = fmaxf(d.w + b1s[c0 + 3], 0.f);
                uint2 hi, lo; split4(h0, h1, h2, h3, hi, lo);
                *(uint2*)&Ahi[row * LDA + c0] = hi;
                *(uint2*)&Alo[row * LDA + c0] = lo;
            }
        }
        __syncthreads();

        // ---- GEMM2 ----
        {
            const int mt = wid >> 1, nt = wid & 1;
            const int m0 = mt * 16, n0 = nt * 16;
            wmma::fragment<wmma::accumulator, 16, 16, 16, float> acc2;
            wmma::fill_fragment(acc2, 0.f);
#pragma unroll
            for (int kk = 0; kk < 8; kk++) {
                const int k0 = kk * 16;
                wmma::fragment<wmma::matrix_a, 16, 16, 16, __nv_bfloat16, wmma::row_major> ah, al;
                wmma::fragment<wmma::matrix_b, 16, 16, 16, __nv_bfloat16, wmma::col_major> bh, bl;
                wmma::load_matrix_sync(ah, &Ahi[m0 * LDA + k0], LDA);
                wmma::load_matrix_sync(al, &Alo[m0 * LDA + k0], LDA);
                wmma::load_matrix_sync(bh, &W2h[n0 * LDA + k0], LDA);
                wmma::load_matrix_sync(bl, &W2l[n0 * LDA + k0], LDA);
                wmma::mma_sync(acc2, ah, bh, acc2);
                wmma::mma_sync(acc2, ah, bl, acc2);
                wmma::mma_sync(acc2, al, bh, acc2);
            }
            wmma::store_matrix_sync(&D[m0 * LDD2 + n0], acc2, LDD2, wmma::mem_row_major);
        }
        __syncthreads();

        // ---- fused epilogue2 (row-per-thread): E=exp(L-rowmax) -> g_L; iter-0 t0 ----
        if (tid < 128) {
            const int grow = row0 + tid;
            const bool valid = (grow < N);
            float* Dr = &D[tid * LDD2];
            float m = -1e30f;
#pragma unroll
            for (int q = 0; q < 8; q++) {
                float4 d = *(const float4*)&Dr[q * 4];
                float l0 = (d.x + b2s[q * 4 + 0]) * sc;
                float l1 = (d.y + b2s[q * 4 + 1]) * sc;
                float l2 = (d.z + b2s[q * 4 + 2]) * sc;
                float l3 = (d.w + b2s[q * 4 + 3]) * sc;
                m = fmaxf(m, fmaxf(fmaxf(l0, l1), fmaxf(l2, l3)));
            }
            float sE = 0.f;
#pragma unroll
            for (int q = 0; q < 8; q++) {
                float4 d = *(const float4*)&Dr[q * 4];
                float4 e;
                e.x = __expf((d.x + b2s[q * 4 + 0]) * sc - m);
                e.y = __expf((d.y + b2s[q * 4 + 1]) * sc - m);
                e.z = __expf((d.z + b2s[q * 4 + 2]) * sc - m);
                e.w = __expf((d.w + b2s[q * 4 + 3]) * sc - m);
                sE += e.x + e.y + e.z + e.w;
                *(float4*)&Dr[q * 4] = e;
                if (valid) *(float4*)&g_L[(size_t)grow * 32 + q * 4] = e;
            }
            if (valid) {
                float r0 = 1.0f / sE;
#pragma unroll
                for (int it2 = 0; it2 < 32; it2++) {
                    int k = (it2 + lane) & 31;    // skew: conflict-free smem atomics
                    atomicAdd(&t0a[k], Dr[k] * r0);
                }
            }
        }
        __syncthreads();
    }

    // publish iter-0 column sums
    if (tid < 32) atomicAdd(&g_t[0][tid], t0a[tid]);
}

// ---------------- persistent Sinkhorn (iterations 1..19) ----------------
__device__ __forceinline__ int eswz(int row, int q) { return (q ^ (row & 7)) << 2; }

__global__ void __launch_bounds__(512, 3)
k_sink(int N, int rpb, unsigned int nb, float NK)
{
    extern __shared__ float smf[];
    float* E = smf;                               // [rpb*32] swizzled (already exp'd)
    float* r = smf + (size_t)rpb * 32;            // [rpb]
    float* c = r + ((rpb + 3) & ~3);              // [32]
    float* red = c + 32;                          // [16*33]

    const int tid = threadIdx.x, lane = tid & 31, wid = tid >> 5;
    const int n0 = blockIdx.x * rpb;
    const int cnt = max(0, min(rpb, N - n0));

    // load E -> swizzled smem (exp already applied by logits kernel)
    for (int f = tid; f < cnt * 8; f += 512) {
        int row = f >> 3, q = f & 7;
        float4 v = *(const float4*)&g_L[(size_t)(n0 + row) * 32 + (q << 2)];
        *(float4*)&E[row * 32 + eswz(row, q)] = v;
    }
    // c0 = NK / t0 (complete by kernel ordering)
    if (tid < 32) c[tid] = NK / __ldcg(&g_t[0][tid]);
    __syncthreads();

    for (int it = 1; it < ITERS; it++) {
        // pass A: r[row] = 1 / sum_k E*c
        for (int row = tid; row < cnt; row += 512) {
            const float* Er = &E[row * 32];
            const int sw = row & 7;
            float s = 0.f;
#pragma unroll
            for (int q = 0; q < 8; q++) {
                float4 t = *(const float4*)(Er + ((q ^ sw) << 2));
                float4 cc = *(const float4*)&c[q << 2];
                s = fmaf(t.x, cc.x, s);
                s = fmaf(t.y, cc.y, s);
                s = fmaf(t.z, cc.z, s);
                s = fmaf(t.w, cc.w, s);
            }
            r[row] = 1.0f / s;
        }
        __syncthreads();

        // pass B: lane-owns-k column sums
        {
            int cpw = (cnt + 15) >> 4;
            int rs = wid * cpw, re = min(rs + cpw, cnt);
            float tlk = 0.f;
            for (int row = rs; row < re; row++) {
                float ev = E[row * 32 + ((((lane >> 2) ^ (row & 7)) << 2) | (lane & 3))];
                tlk = fmaf(ev, r[row], tlk);
            }
            red[wid * 33 + lane] = tlk;
        }
        __syncthreads();
        if (tid < 32) {
            float s = 0.f;
#pragma unroll
            for (int w = 0; w < 16; w++) s += red[w * 33 + tid];
            atomicAdd(&g_t[it][tid], s);
            __threadfence();
        }
        __syncthreads();
        if (tid == 0) {
            atomicAdd(&g_cnt[it], 1u);
            // volatile read + side effect: prevents hoist AND UB-deletion of the
            // spin (root cause of the R9/R10 silent barrier no-op).
            while (*(volatile const unsigned int*)&g_cnt[it] < nb) { __nanosleep(32); }
        }
        __syncthreads();
        if (tid < 32) c[tid] = NK / __ldcg(&g_t[it][tid]);
        __syncthreads();
    }

    // final: S = E*r*c -> overwrite g_L (coalesced)
    for (int f = tid; f < cnt * 8; f += 512) {
        int row = f >> 3, q = f & 7;
        float4 e = *(const float4*)&E[row * 32 + eswz(row, q)];
        float4 cc = *(const float4*)&c[q << 2];
        float rr = r[row];
        float4 o = make_float4(e.x * rr * cc.x, e.y * rr * cc.y,
                               e.z * rr * cc.z, e.w * rr * cc.w);
        *(float4*)&g_L[(size_t)(n0 + row) * 32 + (q << 2)] = o;
    }
}

// ---------------- throughput pooling: out[b] += S^T X (wmma split-bf16) ----------------
__global__ void __launch_bounds__(512)
k_pool(const float* __restrict__ x, const int* __restrict__ batch,
       float* __restrict__ out, int N, int rpp)
{
    __shared__ __nv_bfloat16 shi[16 * 40], slo[16 * 40];
    __shared__ __nv_bfloat16 xhi[16 * 136], xlo[16 * 136];
    __shared__ float Dp[16 * 132];
    __shared__ int bs[16];

    const int tid = threadIdx.x;
    const int wid = tid >> 5;
    const int p0 = blockIdx.x * rpp;
    const int cnt = min(rpp, N - p0);
    if (cnt <= 0) return;

    const int mt = wid & 1;
    const int nt = wid >> 1;
    const int prow = tid >> 5, pq = tid & 31;

    wmma::fragment<wmma::accumulator, 16, 16, 16, float> pacc;
    wmma::fill_fragment(pacc, 0.f);
    int cur_b = -1;

#define POOL_FLUSH(BB) do { \
    __syncthreads(); \
    if (mt == 0) wmma::store_matrix_sync(&Dp[nt * 16], pacc, 132, wmma::mem_row_major); \
    __syncthreads(); \
    for (int f2 = tid; f2 < 2048; f2 += 512) { \
        int mm = f2 >> 7, cc2 = f2 & 127; \
        atomicAdd(&out[(((BB) * 32 + mm) << 7) + cc2], Dp[mm * 132 + cc2]); \
    } \
    __syncthreads(); \
    if (mt == 1) wmma::store_matrix_sync(&Dp[nt * 16], pacc, 132, wmma::mem_row_major); \
    __syncthreads(); \
    for (int f2 = tid; f2 < 2048; f2 += 512) { \
        int mm = f2 >> 7, cc2 = f2 & 127; \
        atomicAdd(&out[(((BB) * 32 + 16 + mm) << 7) + cc2], Dp[mm * 132 + cc2]); \
    } \
    wmma::fill_fragment(pacc, 0.f); \
} while (0)

    float4 xreg = make_float4(0.f, 0.f, 0.f, 0.f);
    float sreg = 0.f;
    int breg = -1;
    if (prow < cnt) {
        xreg = ((const float4*)x)[(size_t)(p0 + prow) * 32 + pq];
        sreg = g_L[(size_t)(p0 + prow) * 32 + pq];
        if (pq == 0) breg = batch[p0 + prow];
    }

    for (int s0 = 0; s0 < cnt; s0 += 16) {
        const int nr = min(16, cnt - s0);
        __syncthreads();
        float scur = (prow < nr) ? sreg : 0.f;
        {
            uint2 hi = make_uint2(0u, 0u), lo = make_uint2(0u, 0u);
            if (prow < nr) split4(xreg.x, xreg.y, xreg.z, xreg.w, hi, lo);
            *(uint2*)&xhi[prow * 136 + pq * 4] = hi;
            *(uint2*)&xlo[prow * 136 + pq * 4] = lo;
            __nv_bfloat16 h = __float2bfloat16(scur);
            shi[prow * 40 + pq] = h;
            slo[prow * 40 + pq] = __float2bfloat16(scur - __bfloat162float(h));
            if (pq == 0) bs[prow] = (prow < nr) ? breg : -1;
        }
        {
            int np = s0 + 16 + prow;
            if (np < cnt) {
                xreg = ((const float4*)x)[(size_t)(p0 + np) * 32 + pq];
                sreg = g_L[(size_t)(p0 + np) * 32 + pq];
                if (pq == 0) breg = batch[p0 + np];
            }
        }
        __syncthreads();

        int pos = 0;
        while (pos < nr) {
            int seg = bs[pos];
            int e = pos + 1;
            while (e < nr && bs[e] == seg) e++;
            if (seg != cur_b) {
                if (cur_b >= 0) POOL_FLUSH(cur_b);
                cur_b = seg;
            }
            bool full = (pos == 0 && e == nr);
            if (!full) {
                __syncthreads();
                float sv = (prow >= pos && prow < e) ? scur : 0.f;
                __nv_bfloat16 h = __float2bfloat16(sv);
                shi[prow * 40 + pq] = h;
                slo[prow * 40 + pq] = __float2bfloat16(sv - __bfloat162float(h));
                __syncthreads();
            }
            wmma::fragment<wmma::matrix_a, 16, 16, 16, __nv_bfloat16, wmma::col_major> sa_h, sa_l;
            wmma::fragment<wmma::matrix_b, 16, 16, 16, __nv_bfloat16, wmma::row_major> xb_h, xb_l;
            wmma::load_matrix_sync(sa_h, &shi[mt * 16], 40);
            wmma::load_matrix_sync(sa_l, &slo[mt * 16], 40);
            wmma::load_matrix_sync(xb_h, &xhi[nt * 16], 136);
            wmma::load_matrix_sync(xb_l, &xlo[nt * 16], 136);
            wmma::mma_sync(pacc, sa_h, xb_h, pacc);
            wmma::mma_sync(pacc, sa_h, xb_l, pacc);
            wmma::mma_sync(pacc, sa_l, xb_h, pacc);
            pos = e;
        }
    }
    if (cur_b >= 0) POOL_FLUSH(cur_b);
#undef POOL_FLUSH
}

// ---------------- launch ----------------
extern "C" void kernel_launch(void* const* d_in, const int* in_sizes, int n_in,
                              void* d_out, int out_size)
{
    const float* x       = (const float*)d_in[0];
    const int*   batch   = (const int*)d_in[1];
    const float* W1      = (const float*)d_in[2];
    const float* b1      = (const float*)d_in[3];
    const float* W2      = (const float*)d_in[4];
    const float* b2      = (const float*)d_in[5];
    const float* scaling = (const float*)d_in[6];

    const int N = in_sizes[0] / C_DIM;

    int dev = 0, nsm = 148;
    cudaGetDevice(&dev);
    cudaDeviceGetAttribute(&nsm, cudaDevAttrMultiProcessorCount, dev);

    const int ntiles = (N + 127) >> 7;
    const int gl = ntiles < nsm ? ntiles : nsm;

    auto sink_smem = [](int rpb) -> size_t {
        return ((size_t)rpb * 32 + ((rpb + 3) & ~3) + 32 + 528 + 16) * 4;
    };
    const int nb3 = nsm * 3, nb2 = nsm * 2, nb1 = nsm;
    const int rpb3 = (N + nb3 - 1) / nb3;
    const int rpb2 = (N + nb2 - 1) / nb2;
    const int rpb1 = (N + nb1 - 1) / nb1;
    const size_t sm3 = sink_smem(rpb3), sm2 = sink_smem(rpb2), sm1 = sink_smem(rpb1);

    cudaFuncSetAttribute(k_logits_tc, cudaFuncAttributeMaxDynamicSharedMemorySize, SMEM_TC);
    cudaFuncSetAttribute(k_sink, cudaFuncAttributeMaxDynamicSharedMemorySize, (int)sm1);

    int o3 = 0, o2 = 0;
    cudaOccupancyMaxActiveBlocksPerMultiprocessor(&o3, k_sink, 512, sm3);
    cudaOccupancyMaxActiveBlocksPerMultiprocessor(&o2, k_sink, 512, sm2);

    int nb, rpb; size_t sms;
    if (o3 >= 3)      { nb = nb3; rpb = rpb3; sms = sm3; }
    else if (o2 >= 2) { nb = nb2; rpb = rpb2; sms = sm2; }
    else              { nb = nb1; rpb = rpb1; sms = sm1; }

    int rpp = ((N + nsm * 4 - 1) / (nsm * 4) + 15) & ~15;
    int G = (N + rpp - 1) / rpp;

    void* gt_addr = nullptr; void* gc_addr = nullptr;
    cudaGetSymbolAddress(&gt_addr, g_t);
    cudaGetSymbolAddress(&gc_addr, g_cnt);
    cudaMemsetAsync(gt_addr, 0, sizeof(float) * ITERS * K_DIM);
    cudaMemsetAsync(gc_addr, 0, sizeof(unsigned int) * ITERS);
    cudaMemsetAsync(d_out, 0, (size_t)out_size * sizeof(float));

    k_logits_tc<<<gl, 512, SMEM_TC>>>(x, W1, b1, W2, b2, scaling, N, ntiles);

    const float NK = (float)N / (float)K_DIM + 1e-9f;
    k_sink<<<nb, 512, sms>>>(N, rpb, (unsigned)nb, NK);
    k_pool<<<G, 512>>>(x, batch, (float*)d_out, N, rpp);
}

// round 13
// speedup vs baseline: 1.1726x; 1.1726x over previous
#include <cuda_runtime.h>
#include <cuda_bf16.h>
#include <mma.h>
#include <math.h>
#include <stdint.h>

using namespace nvcuda;

// Problem constants (dataset-fixed): C=128, K=32, N=200000, B=16.
#define C_DIM 128
#define K_DIM 32
#define N_MAX 200704
#define ITERS 20

// ---------------- scratch ----------------
__device__ float g_L[(size_t)N_MAX * K_DIM];   // raw logits (kept through pool)
__device__ float g_r[N_MAX];                   // final row factors (from sink)
__device__ float g_m[N_MAX];                   // per-row logit max (from sink)
__device__ float g_t[ITERS][K_DIM];            // per-iter column sums
__device__ unsigned int g_cnt[ITERS];          // per-iter arrival counters

// split 4 consecutive floats into hi/lo bf16x2 pairs
__device__ __forceinline__ void split4(float a, float b, float c, float d, uint2& hi, uint2& lo) {
    __nv_bfloat162 h0 = __floats2bfloat162_rn(a, b);
    __nv_bfloat162 h1 = __floats2bfloat162_rn(c, d);
    __nv_bfloat162 l0 = __floats2bfloat162_rn(a - __low2float(h0), b - __high2float(h0));
    __nv_bfloat162 l1 = __floats2bfloat162_rn(c - __low2float(h1), d - __high2float(h1));
    hi.x = *reinterpret_cast<uint32_t*>(&h0);
    hi.y = *reinterpret_cast<uint32_t*>(&h1);
    lo.x = *reinterpret_cast<uint32_t*>(&l0);
    lo.y = *reinterpret_cast<uint32_t*>(&l1);
}

// ================= persistent wmma MLP -> logits (R11-proven) =================
#define LDA 136
#define LDD 132
#define LDD2 36
#define OF_AHI  0
#define OF_ALO  (OF_AHI + 128 * LDA * 2)
#define OF_W1HI (OF_ALO + 128 * LDA * 2)
#define OF_W1LO (OF_W1HI + 128 * LDA * 2)
#define OF_W2HI (OF_W1LO + 128 * LDA * 2)
#define OF_W2LO (OF_W2HI + 32 * LDA * 2)
#define OF_D    (OF_W2LO + 32 * LDA * 2)
#define OF_B1   (OF_D + 128 * LDD * 4)
#define OF_B2   (OF_B1 + 512)
#define SMEM_TC (OF_B2 + 128)

__global__ void __launch_bounds__(512, 1)
k_logits_tc(const float* __restrict__ x, const float* __restrict__ W1,
            const float* __restrict__ b1, const float* __restrict__ W2,
            const float* __restrict__ b2, const float* __restrict__ scaling,
            int N, int ntiles)
{
    extern __shared__ char sm[];
    __nv_bfloat16* Ahi = (__nv_bfloat16*)(sm + OF_AHI);
    __nv_bfloat16* Alo = (__nv_bfloat16*)(sm + OF_ALO);
    __nv_bfloat16* W1h = (__nv_bfloat16*)(sm + OF_W1HI);
    __nv_bfloat16* W1l = (__nv_bfloat16*)(sm + OF_W1LO);
    __nv_bfloat16* W2h = (__nv_bfloat16*)(sm + OF_W2HI);
    __nv_bfloat16* W2l = (__nv_bfloat16*)(sm + OF_W2LO);
    float* D   = (float*)(sm + OF_D);
    float* b1s = (float*)(sm + OF_B1);
    float* b2s = (float*)(sm + OF_B2);

    const int tid = threadIdx.x, wid = tid >> 5, lane = tid & 31;
    const float sc = __ldg(scaling);

    for (int f = tid; f < 4096; f += 512) {
        int j = f & 127, k0 = (f >> 7) << 2;
        float v0 = W1[(k0 + 0) * 128 + j], v1 = W1[(k0 + 1) * 128 + j];
        float v2 = W1[(k0 + 2) * 128 + j], v3 = W1[(k0 + 3) * 128 + j];
        uint2 hi, lo; split4(v0, v1, v2, v3, hi, lo);
        *(uint2*)&W1h[j * LDA + k0] = hi;
        *(uint2*)&W1l[j * LDA + k0] = lo;
    }
    for (int f = tid; f < 1024; f += 512) {
        int j = f & 31, k0 = (f >> 5) << 2;
        float v0 = W2[(k0 + 0) * 32 + j], v1 = W2[(k0 + 1) * 32 + j];
        float v2 = W2[(k0 + 2) * 32 + j], v3 = W2[(k0 + 3) * 32 + j];
        uint2 hi, lo; split4(v0, v1, v2, v3, hi, lo);
        *(uint2*)&W2h[j * LDA + k0] = hi;
        *(uint2*)&W2l[j * LDA + k0] = lo;
    }
    if (tid < 128) b1s[tid] = b1[tid];
    else if (tid < 160) b2s[tid - 128] = b2[tid - 128];
    __syncthreads();

    for (int t = blockIdx.x; t < ntiles; t += gridDim.x) {
        const int row0 = t << 7;

        // ---- x tile: inline load + split ----
#pragma unroll
        for (int i = 0; i < 8; i++) {
            int f = tid + i * 512;
            int row = f >> 5, c0 = (f & 31) << 2;
            int rr = row0 + row;
            float4 v = (rr < N) ? ((const float4*)x)[(size_t)rr * 32 + (c0 >> 2)]
                                : make_float4(0.f, 0.f, 0.f, 0.f);
            uint2 hi, lo; split4(v.x, v.y, v.z, v.w, hi, lo);
            *(uint2*)&Ahi[row * LDA + c0] = hi;
            *(uint2*)&Alo[row * LDA + c0] = lo;
        }
        __syncthreads();

        // ---- GEMM1 ----
        {
            const int wm = wid >> 2, wn = wid & 3;
            const int m0 = wm * 32, n0 = wn * 32;
            wmma::fragment<wmma::accumulator, 16, 16, 16, float> acc[2][2];
#pragma unroll
            for (int i = 0; i < 2; i++)
#pragma unroll
                for (int j = 0; j < 2; j++) wmma::fill_fragment(acc[i][j], 0.f);
#pragma unroll
            for (int kk = 0; kk < 8; kk++) {
                const int k0 = kk * 16;
                wmma::fragment<wmma::matrix_a, 16, 16, 16, __nv_bfloat16, wmma::row_major> ah[2], al[2];
#pragma unroll
                for (int i = 0; i < 2; i++) {
                    wmma::load_matrix_sync(ah[i], &Ahi[(m0 + i * 16) * LDA + k0], LDA);
                    wmma::load_matrix_sync(al[i], &Alo[(m0 + i * 16) * LDA + k0], LDA);
                }
#pragma unroll
                for (int j = 0; j < 2; j++) {
                    wmma::fragment<wmma::matrix_b, 16, 16, 16, __nv_bfloat16, wmma::col_major> bh, bl;
                    wmma::load_matrix_sync(bh, &W1h[(n0 + j * 16) * LDA + k0], LDA);
                    wmma::load_matrix_sync(bl, &W1l[(n0 + j * 16) * LDA + k0], LDA);
#pragma unroll
                    for (int i = 0; i < 2; i++) {
                        wmma::mma_sync(acc[i][j], ah[i], bh, acc[i][j]);
                        wmma::mma_sync(acc[i][j], ah[i], bl, acc[i][j]);
                        wmma::mma_sync(acc[i][j], al[i], bh, acc[i][j]);
                    }
                }
            }
#pragma unroll
            for (int i = 0; i < 2; i++)
#pragma unroll
                for (int j = 0; j < 2; j++)
                    wmma::store_matrix_sync(&D[(m0 + i * 16) * LDD + n0 + j * 16], acc[i][j],
                                            LDD, wmma::mem_row_major);
        }
        __syncthreads();

        // ---- epilogue1: h = relu(D1+b1) -> re-split into A ----
        {
            const int row = tid >> 2, cb = (tid & 3) * 32;
#pragma unroll
            for (int g = 0; g < 8; g++) {
                int c0 = cb + g * 4;
                float4 d = *(const float4*)&D[row * LDD + c0];
                float h0 = fmaxf(d.x + b1s[c0 + 0], 0.f);
                float h1 = fmaxf(d.y + b1s[c0 + 1], 0.f);
                float h2 = fmaxf(d.z + b1s[c0 + 2], 0.f);
                float h3 = fmaxf(d.w + b1s[c0 + 3], 0.f);
                uint2 hi, lo; split4(h0, h1, h2, h3, hi, lo);
                *(uint2*)&Ahi[row * LDA + c0] = hi;
                *(uint2*)&Alo[row * LDA + c0] = lo;
            }
        }
        __syncthreads();

        // ---- GEMM2 + fused warp-local epilogue2 ----
        {
            const int mt = wid >> 1, nt = wid & 1;
            const int m0 = mt * 16, n0 = nt * 16;
            wmma::fragment<wmma::accumulator, 16, 16, 16, float> acc2;
            wmma::fill_fragment(acc2, 0.f);
#pragma unroll
            for (int kk = 0; kk < 8; kk++) {
                const int k0 = kk * 16;
                wmma::fragment<wmma::matrix_a, 16, 16, 16, __nv_bfloat16, wmma::row_major> ah, al;
                wmma::fragment<wmma::matrix_b, 16, 16, 16, __nv_bfloat16, wmma::col_major> bh, bl;
                wmma::load_matrix_sync(ah, &Ahi[m0 * LDA + k0], LDA);
                wmma::load_matrix_sync(al, &Alo[m0 * LDA + k0], LDA);
                wmma::load_matrix_sync(bh, &W2h[n0 * LDA + k0], LDA);
                wmma::load_matrix_sync(bl, &W2l[n0 * LDA + k0], LDA);
                wmma::mma_sync(acc2, ah, bh, acc2);
                wmma::mma_sync(acc2, ah, bl, acc2);
                wmma::mma_sync(acc2, al, bh, acc2);
            }
            wmma::store_matrix_sync(&D[m0 * LDD2 + n0], acc2, LDD2, wmma::mem_row_major);
            __syncwarp();
            const int r2 = lane >> 1, cq = lane & 1;
            const int row = m0 + r2;
            const int grow = row0 + row;
            if (grow < N) {
                const int c0 = n0 + cq * 8;
                float4 d0 = *(const float4*)&D[row * LDD2 + c0];
                float4 d1 = *(const float4*)&D[row * LDD2 + c0 + 4];
                float4 o0 = make_float4((d0.x + b2s[c0 + 0]) * sc, (d0.y + b2s[c0 + 1]) * sc,
                                        (d0.z + b2s[c0 + 2]) * sc, (d0.w + b2s[c0 + 3]) * sc);
                float4 o1 = make_float4((d1.x + b2s[c0 + 4]) * sc, (d1.y + b2s[c0 + 5]) * sc,
                                        (d1.z + b2s[c0 + 6]) * sc, (d1.w + b2s[c0 + 7]) * sc);
                *(float4*)&g_L[(size_t)grow * 32 + c0] = o0;
                *(float4*)&g_L[(size_t)grow * 32 + c0 + 4] = o1;
            }
        }
        __syncthreads();
    }
}

// ---------------- persistent Sinkhorn ----------------
__device__ __forceinline__ int eswz(int row, int q) { return (q ^ (row & 7)) << 2; }

__global__ void __launch_bounds__(512, 3)
k_sink(int N, int rpb, unsigned int nb, float NK)
{
    extern __shared__ float smf[];
    float* E = smf;                               // [rpb*32] swizzled
    float* r = smf + (size_t)rpb * 32;            // [rpb]
    float* msm = r + ((rpb + 3) & ~3);            // [rpb] rowmax
    float* c = msm + ((rpb + 3) & ~3);            // [32]
    float* red = c + 32;                          // [16*33]

    const int tid = threadIdx.x, lane = tid & 31, wid = tid >> 5;
    const int n0 = blockIdx.x * rpb;
    const int cnt = max(0, min(rpb, N - n0));

    // load logits -> swizzled E
    for (int f = tid; f < cnt * 8; f += 512) {
        int row = f >> 3, q = f & 7;
        float4 v = *(const float4*)&g_L[(size_t)(n0 + row) * 32 + (q << 2)];
        *(float4*)&E[row * 32 + eswz(row, q)] = v;
    }
    if (tid < 32) c[tid] = 1.f;
    __syncthreads();

    // E = exp(L - rowmax), remember rowmax
    for (int row = tid; row < cnt; row += 512) {
        float* Er = &E[row * 32];
        const int sw = row & 7;
        float e[32];
        float m = -1e30f;
#pragma unroll
        for (int q = 0; q < 8; q++) {
            float4 t = *(const float4*)(Er + ((q ^ sw) << 2));
            e[4*q] = t.x; e[4*q+1] = t.y; e[4*q+2] = t.z; e[4*q+3] = t.w;
            m = fmaxf(m, fmaxf(fmaxf(t.x, t.y), fmaxf(t.z, t.w)));
        }
        msm[row] = m;
#pragma unroll
        for (int q = 0; q < 8; q++) {
            float4 t;
            t.x = __expf(e[4*q] - m);   t.y = __expf(e[4*q+1] - m);
            t.z = __expf(e[4*q+2] - m); t.w = __expf(e[4*q+3] - m);
            *(float4*)(Er + ((q ^ sw) << 2)) = t;
        }
    }
    __syncthreads();

    for (int it = 0; it < ITERS; it++) {
        // pass A: r[row] = 1 / sum_k E*c
        for (int row = tid; row < cnt; row += 512) {
            const float* Er = &E[row * 32];
            const int sw = row & 7;
            float s = 0.f;
#pragma unroll
            for (int q = 0; q < 8; q++) {
                float4 t = *(const float4*)(Er + ((q ^ sw) << 2));
                float4 cc = *(const float4*)&c[q << 2];
                s = fmaf(t.x, cc.x, s);
                s = fmaf(t.y, cc.y, s);
                s = fmaf(t.z, cc.z, s);
                s = fmaf(t.w, cc.w, s);
            }
            r[row] = 1.0f / s;
        }
        __syncthreads();

        // pass B: lane-owns-k column sums
        {
            int cpw = (cnt + 15) >> 4;
            int rs = wid * cpw, re = min(rs + cpw, cnt);
            float tlk = 0.f;
            for (int row = rs; row < re; row++) {
                float ev = E[row * 32 + ((((lane >> 2) ^ (row & 7)) << 2) | (lane & 3))];
                tlk = fmaf(ev, r[row], tlk);
            }
            red[wid * 33 + lane] = tlk;
        }
        __syncthreads();
        if (tid < 32) {
            float s = 0.f;
#pragma unroll
            for (int w = 0; w < 16; w++) s += red[w * 33 + tid];
            atomicAdd(&g_t[it][tid], s);
            __threadfence();
        }
        __syncthreads();
        if (tid == 0) {
            atomicAdd(&g_cnt[it], 1u);
            // volatile read + side effect: prevents hoist AND UB-deletion of the
            // spin (root cause of the R9/R10 silent barrier no-op).
            while (*(volatile const unsigned int*)&g_cnt[it] < nb) { __nanosleep(32); }
        }
        __syncthreads();
        if (tid < 32) c[tid] = NK / __ldcg(&g_t[it][tid]);
        __syncthreads();
    }

    // publish r (final pass-A result) and rowmax; pool reconstructs S on the fly
    for (int row = tid; row < cnt; row += 512) {
        g_r[n0 + row] = r[row];
        g_m[n0 + row] = msm[row];
    }
}

// ---------------- throughput pooling: out[b] += S^T X, S = exp(L-m)*r*c ----------------
__global__ void __launch_bounds__(512)
k_pool(const float* __restrict__ x, const int* __restrict__ batch,
       float* __restrict__ out, int N, int rpp, float NK)
{
    __shared__ __nv_bfloat16 shi[16 * 40], slo[16 * 40];
    __shared__ __nv_bfloat16 xhi[16 * 136], xlo[16 * 136];
    __shared__ float Dp[16 * 132];
    __shared__ float cpool[32];
    __shared__ int bs[16];

    const int tid = threadIdx.x;
    const int wid = tid >> 5;
    const int p0 = blockIdx.x * rpp;
    const int cnt = min(rpp, N - p0);
    if (cnt <= 0) return;

    const int mt = wid & 1;
    const int nt = wid >> 1;
    const int prow = tid >> 5, pq = tid & 31;

    if (tid < 32) cpool[tid] = NK / __ldcg(&g_t[ITERS - 1][tid]);

    wmma::fragment<wmma::accumulator, 16, 16, 16, float> pacc;
    wmma::fill_fragment(pacc, 0.f);
    int cur_b = -1;

#define POOL_FLUSH(BB) do { \
    __syncthreads(); \
    if (mt == 0) wmma::store_matrix_sync(&Dp[nt * 16], pacc, 132, wmma::mem_row_major); \
    __syncthreads(); \
    for (int f2 = tid; f2 < 2048; f2 += 512) { \
        int mm = f2 >> 7, cc2 = f2 & 127; \
        atomicAdd(&out[(((BB) * 32 + mm) << 7) + cc2], Dp[mm * 132 + cc2]); \
    } \
    __syncthreads(); \
    if (mt == 1) wmma::store_matrix_sync(&Dp[nt * 16], pacc, 132, wmma::mem_row_major); \
    __syncthreads(); \
    for (int f2 = tid; f2 < 2048; f2 += 512) { \
        int mm = f2 >> 7, cc2 = f2 & 127; \
        atomicAdd(&out[(((BB) * 32 + 16 + mm) << 7) + cc2], Dp[mm * 132 + cc2]); \
    } \
    wmma::fill_fragment(pacc, 0.f); \
} while (0)

    // prefetch chunk 0
    float4 xreg = make_float4(0.f, 0.f, 0.f, 0.f);
    float lreg = 0.f, rreg = 0.f, mreg = 0.f;
    int breg = -1;
    if (prow < cnt) {
        xreg = ((const float4*)x)[(size_t)(p0 + prow) * 32 + pq];
        lreg = g_L[(size_t)(p0 + prow) * 32 + pq];
        rreg = g_r[p0 + prow];
        mreg = g_m[p0 + prow];
        if (pq == 0) breg = batch[p0 + prow];
    }

    for (int s0 = 0; s0 < cnt; s0 += 16) {
        const int nr = min(16, cnt - s0);
        __syncthreads();
        float scur = (prow < nr) ? __expf(lreg - mreg) * rreg * cpool[pq] : 0.f;
        {
            uint2 hi = make_uint2(0u, 0u), lo = make_uint2(0u, 0u);
            if (prow < nr) split4(xreg.x, xreg.y, xreg.z, xreg.w, hi, lo);
            *(uint2*)&xhi[prow * 136 + pq * 4] = hi;
            *(uint2*)&xlo[prow * 136 + pq * 4] = lo;
            __nv_bfloat16 h = __float2bfloat16(scur);
            shi[prow * 40 + pq] = h;
            slo[prow * 40 + pq] = __float2bfloat16(scur - __bfloat162float(h));
            if (pq == 0) bs[prow] = (prow < nr) ? breg : -1;
        }
        // prefetch next chunk
        {
            int np = s0 + 16 + prow;
            if (np < cnt) {
                xreg = ((const float4*)x)[(size_t)(p0 + np) * 32 + pq];
                lreg = g_L[(size_t)(p0 + np) * 32 + pq];
                rreg = g_r[p0 + np];
                mreg = g_m[p0 + np];
                if (pq == 0) breg = batch[p0 + np];
            }
        }
        __syncthreads();

        int pos = 0;
        while (pos < nr) {
            int seg = bs[pos];
            int e = pos + 1;
            while (e < nr && bs[e] == seg) e++;
            if (seg != cur_b) {
                if (cur_b >= 0) POOL_FLUSH(cur_b);
                cur_b = seg;
            }
            bool full = (pos == 0 && e == nr);
            if (!full) {
                __syncthreads();
                float sv = (prow >= pos && prow < e) ? scur : 0.f;
                __nv_bfloat16 h = __float2bfloat16(sv);
                shi[prow * 40 + pq] = h;
                slo[prow * 40 + pq] = __float2bfloat16(sv - __bfloat162float(h));
                __syncthreads();
            }
            wmma::fragment<wmma::matrix_a, 16, 16, 16, __nv_bfloat16, wmma::col_major> sa_h, sa_l;
            wmma::fragment<wmma::matrix_b, 16, 16, 16, __nv_bfloat16, wmma::row_major> xb_h, xb_l;
            wmma::load_matrix_sync(sa_h, &shi[mt * 16], 40);
            wmma::load_matrix_sync(sa_l, &slo[mt * 16], 40);
            wmma::load_matrix_sync(xb_h, &xhi[nt * 16], 136);
            wmma::load_matrix_sync(xb_l, &xlo[nt * 16], 136);
            wmma::mma_sync(pacc, sa_h, xb_h, pacc);
            wmma::mma_sync(pacc, sa_h, xb_l, pacc);
            wmma::mma_sync(pacc, sa_l, xb_h, pacc);
            pos = e;
        }
    }
    if (cur_b >= 0) POOL_FLUSH(cur_b);
#undef POOL_FLUSH
}

// ---------------- launch ----------------
extern "C" void kernel_launch(void* const* d_in, const int* in_sizes, int n_in,
                              void* d_out, int out_size)
{
    const float* x       = (const float*)d_in[0];
    const int*   batch   = (const int*)d_in[1];
    const float* W1      = (const float*)d_in[2];
    const float* b1      = (const float*)d_in[3];
    const float* W2      = (const float*)d_in[4];
    const float* b2      = (const float*)d_in[5];
    const float* scaling = (const float*)d_in[6];

    const int N = in_sizes[0] / C_DIM;

    int dev = 0, nsm = 148;
    cudaGetDevice(&dev);
    cudaDeviceGetAttribute(&nsm, cudaDevAttrMultiProcessorCount, dev);

    const int ntiles = (N + 127) >> 7;
    const int gl = ntiles < nsm ? ntiles : nsm;

    // sink smem: E rpb*32 + r + m (padded) + c 32 + red 528 + pad
    auto sink_smem = [](int rpb) -> size_t {
        return ((size_t)rpb * 32 + 2 * (size_t)((rpb + 3) & ~3) + 32 + 528 + 16) * 4;
    };
    const int nb3 = nsm * 3, nb2 = nsm * 2, nb1 = nsm;
    const int rpb3 = (N + nb3 - 1) / nb3;
    const int rpb2 = (N + nb2 - 1) / nb2;
    const int rpb1 = (N + nb1 - 1) / nb1;
    const size_t sm3 = sink_smem(rpb3), sm2 = sink_smem(rpb2), sm1 = sink_smem(rpb1);

    cudaFuncSetAttribute(k_logits_tc, cudaFuncAttributeMaxDynamicSharedMemorySize, SMEM_TC);
    cudaFuncSetAttribute(k_sink, cudaFuncAttributeMaxDynamicSharedMemorySize, (int)sm1);

    int o3 = 0, o2 = 0;
    cudaOccupancyMaxActiveBlocksPerMultiprocessor(&o3, k_sink, 512, sm3);
    cudaOccupancyMaxActiveBlocksPerMultiprocessor(&o2, k_sink, 512, sm2);

    int nb, rpb; size_t sms;
    if (o3 >= 3)      { nb = nb3; rpb = rpb3; sms = sm3; }
    else if (o2 >= 2) { nb = nb2; rpb = rpb2; sms = sm2; }
    else              { nb = nb1; rpb = rpb1; sms = sm1; }

    int rpp = ((N + nsm * 4 - 1) / (nsm * 4) + 15) & ~15;
    int G = (N + rpp - 1) / rpp;

    void* gt_addr = nullptr; void* gc_addr = nullptr;
    cudaGetSymbolAddress(&gt_addr, g_t);
    cudaGetSymbolAddress(&gc_addr, g_cnt);
    cudaMemsetAsync(gt_addr, 0, sizeof(float) * ITERS * K_DIM);
    cudaMemsetAsync(gc_addr, 0, sizeof(unsigned int) * ITERS);
    cudaMemsetAsync(d_out, 0, (size_t)out_size * sizeof(float));

    k_logits_tc<<<gl, 512, SMEM_TC>>>(x, W1, b1, W2, b2, scaling, N, ntiles);

    const float NK = (float)N / (float)K_DIM + 1e-9f;
    k_sink<<<nb, 512, sms>>>(N, rpb, (unsigned)nb, NK);
    k_pool<<<G, 512, 0>>>(x, batch, (float*)d_out, N, rpp, NK);
}

// round 14
// speedup vs baseline: 1.1728x; 1.0002x over previous
#include <cuda_runtime.h>
#include <cuda_bf16.h>
#include <mma.h>
#include <math.h>
#include <stdint.h>

using namespace nvcuda;

// Problem constants (dataset-fixed): C=128, K=32, N=200000, B=16.
#define C_DIM 128
#define K_DIM 32
#define N_MAX 200704
#define ITERS 20

// ---------------- scratch ----------------
__device__ float g_L[(size_t)N_MAX * K_DIM];   // raw logits (kept through pool)
__device__ float g_r[N_MAX];                   // final row factors (from sink)
__device__ float g_m[N_MAX];                   // per-row logit max (from sink)
__device__ float g_t[ITERS][K_DIM];            // per-iter column sums
__device__ unsigned int g_cnt[ITERS];          // per-iter arrival counters

// split 4 consecutive floats into hi/lo bf16x2 pairs
__device__ __forceinline__ void split4(float a, float b, float c, float d, uint2& hi, uint2& lo) {
    __nv_bfloat162 h0 = __floats2bfloat162_rn(a, b);
    __nv_bfloat162 h1 = __floats2bfloat162_rn(c, d);
    __nv_bfloat162 l0 = __floats2bfloat162_rn(a - __low2float(h0), b - __high2float(h0));
    __nv_bfloat162 l1 = __floats2bfloat162_rn(c - __low2float(h1), d - __high2float(h1));
    hi.x = *reinterpret_cast<uint32_t*>(&h0);
    hi.y = *reinterpret_cast<uint32_t*>(&h1);
    lo.x = *reinterpret_cast<uint32_t*>(&l0);
    lo.y = *reinterpret_cast<uint32_t*>(&l1);
}

// ================= persistent wmma MLP -> logits (R11/R13-proven, untouched) =================
#define LDA 136
#define LDD 132
#define LDD2 36
#define OF_AHI  0
#define OF_ALO  (OF_AHI + 128 * LDA * 2)
#define OF_W1HI (OF_ALO + 128 * LDA * 2)
#define OF_W1LO (OF_W1HI + 128 * LDA * 2)
#define OF_W2HI (OF_W1LO + 128 * LDA * 2)
#define OF_W2LO (OF_W2HI + 32 * LDA * 2)
#define OF_D    (OF_W2LO + 32 * LDA * 2)
#define OF_B1   (OF_D + 128 * LDD * 4)
#define OF_B2   (OF_B1 + 512)
#define SMEM_TC (OF_B2 + 128)

__global__ void __launch_bounds__(512, 1)
k_logits_tc(const float* __restrict__ x, const float* __restrict__ W1,
            const float* __restrict__ b1, const float* __restrict__ W2,
            const float* __restrict__ b2, const float* __restrict__ scaling,
            int N, int ntiles)
{
    extern __shared__ char sm[];
    __nv_bfloat16* Ahi = (__nv_bfloat16*)(sm + OF_AHI);
    __nv_bfloat16* Alo = (__nv_bfloat16*)(sm + OF_ALO);
    __nv_bfloat16* W1h = (__nv_bfloat16*)(sm + OF_W1HI);
    __nv_bfloat16* W1l = (__nv_bfloat16*)(sm + OF_W1LO);
    __nv_bfloat16* W2h = (__nv_bfloat16*)(sm + OF_W2HI);
    __nv_bfloat16* W2l = (__nv_bfloat16*)(sm + OF_W2LO);
    float* D   = (float*)(sm + OF_D);
    float* b1s = (float*)(sm + OF_B1);
    float* b2s = (float*)(sm + OF_B2);

    const int tid = threadIdx.x, wid = tid >> 5, lane = tid & 31;
    const float sc = __ldg(scaling);

    for (int f = tid; f < 4096; f += 512) {
        int j = f & 127, k0 = (f >> 7) << 2;
        float v0 = W1[(k0 + 0) * 128 + j], v1 = W1[(k0 + 1) * 128 + j];
        float v2 = W1[(k0 + 2) * 128 + j], v3 = W1[(k0 + 3) * 128 + j];
        uint2 hi, lo; split4(v0, v1, v2, v3, hi, lo);
        *(uint2*)&W1h[j * LDA + k0] = hi;
        *(uint2*)&W1l[j * LDA + k0] = lo;
    }
    for (int f = tid; f < 1024; f += 512) {
        int j = f & 31, k0 = (f >> 5) << 2;
        float v0 = W2[(k0 + 0) * 32 + j], v1 = W2[(k0 + 1) * 32 + j];
        float v2 = W2[(k0 + 2) * 32 + j], v3 = W2[(k0 + 3) * 32 + j];
        uint2 hi, lo; split4(v0, v1, v2, v3, hi, lo);
        *(uint2*)&W2h[j * LDA + k0] = hi;
        *(uint2*)&W2l[j * LDA + k0] = lo;
    }
    if (tid < 128) b1s[tid] = b1[tid];
    else if (tid < 160) b2s[tid - 128] = b2[tid - 128];
    __syncthreads();

    for (int t = blockIdx.x; t < ntiles; t += gridDim.x) {
        const int row0 = t << 7;

        // ---- x tile: inline load + split ----
#pragma unroll
        for (int i = 0; i < 8; i++) {
            int f = tid + i * 512;
            int row = f >> 5, c0 = (f & 31) << 2;
            int rr = row0 + row;
            float4 v = (rr < N) ? ((const float4*)x)[(size_t)rr * 32 + (c0 >> 2)]
                                : make_float4(0.f, 0.f, 0.f, 0.f);
            uint2 hi, lo; split4(v.x, v.y, v.z, v.w, hi, lo);
            *(uint2*)&Ahi[row * LDA + c0] = hi;
            *(uint2*)&Alo[row * LDA + c0] = lo;
        }
        __syncthreads();

        // ---- GEMM1 ----
        {
            const int wm = wid >> 2, wn = wid & 3;
            const int m0 = wm * 32, n0 = wn * 32;
            wmma::fragment<wmma::accumulator, 16, 16, 16, float> acc[2][2];
#pragma unroll
            for (int i = 0; i < 2; i++)
#pragma unroll
                for (int j = 0; j < 2; j++) wmma::fill_fragment(acc[i][j], 0.f);
#pragma unroll
            for (int kk = 0; kk < 8; kk++) {
                const int k0 = kk * 16;
                wmma::fragment<wmma::matrix_a, 16, 16, 16, __nv_bfloat16, wmma::row_major> ah[2], al[2];
#pragma unroll
                for (int i = 0; i < 2; i++) {
                    wmma::load_matrix_sync(ah[i], &Ahi[(m0 + i * 16) * LDA + k0], LDA);
                    wmma::load_matrix_sync(al[i], &Alo[(m0 + i * 16) * LDA + k0], LDA);
                }
#pragma unroll
                for (int j = 0; j < 2; j++) {
                    wmma::fragment<wmma::matrix_b, 16, 16, 16, __nv_bfloat16, wmma::col_major> bh, bl;
                    wmma::load_matrix_sync(bh, &W1h[(n0 + j * 16) * LDA + k0], LDA);
                    wmma::load_matrix_sync(bl, &W1l[(n0 + j * 16) * LDA + k0], LDA);
#pragma unroll
                    for (int i = 0; i < 2; i++) {
                        wmma::mma_sync(acc[i][j], ah[i], bh, acc[i][j]);
                        wmma::mma_sync(acc[i][j], ah[i], bl, acc[i][j]);
                        wmma::mma_sync(acc[i][j], al[i], bh, acc[i][j]);
                    }
                }
            }
#pragma unroll
            for (int i = 0; i < 2; i++)
#pragma unroll
                for (int j = 0; j < 2; j++)
                    wmma::store_matrix_sync(&D[(m0 + i * 16) * LDD + n0 + j * 16], acc[i][j],
                                            LDD, wmma::mem_row_major);
        }
        __syncthreads();

        // ---- epilogue1: h = relu(D1+b1) -> re-split into A ----
        {
            const int row = tid >> 2, cb = (tid & 3) * 32;
#pragma unroll
            for (int g = 0; g < 8; g++) {
                int c0 = cb + g * 4;
                float4 d = *(const float4*)&D[row * LDD + c0];
                float h0 = fmaxf(d.x + b1s[c0 + 0], 0.f);
                float h1 = fmaxf(d.y + b1s[c0 + 1], 0.f);
                float h2 = fmaxf(d.z + b1s[c0 + 2], 0.f);
                float h3 = fmaxf(d.w + b1s[c0 + 3], 0.f);
                uint2 hi, lo; split4(h0, h1, h2, h3, hi, lo);
                *(uint2*)&Ahi[row * LDA + c0] = hi;
                *(uint2*)&Alo[row * LDA + c0] = lo;
            }
        }
        __syncthreads();

        // ---- GEMM2 + fused warp-local epilogue2 ----
        {
            const int mt = wid >> 1, nt = wid & 1;
            const int m0 = mt * 16, n0 = nt * 16;
            wmma::fragment<wmma::accumulator, 16, 16, 16, float> acc2;
            wmma::fill_fragment(acc2, 0.f);
#pragma unroll
            for (int kk = 0; kk < 8; kk++) {
                const int k0 = kk * 16;
                wmma::fragment<wmma::matrix_a, 16, 16, 16, __nv_bfloat16, wmma::row_major> ah, al;
                wmma::fragment<wmma::matrix_b, 16, 16, 16, __nv_bfloat16, wmma::col_major> bh, bl;
                wmma::load_matrix_sync(ah, &Ahi[m0 * LDA + k0], LDA);
                wmma::load_matrix_sync(al, &Alo[m0 * LDA + k0], LDA);
                wmma::load_matrix_sync(bh, &W2h[n0 * LDA + k0], LDA);
                wmma::load_matrix_sync(bl, &W2l[n0 * LDA + k0], LDA);
                wmma::mma_sync(acc2, ah, bh, acc2);
                wmma::mma_sync(acc2, ah, bl, acc2);
                wmma::mma_sync(acc2, al, bh, acc2);
            }
            wmma::store_matrix_sync(&D[m0 * LDD2 + n0], acc2, LDD2, wmma::mem_row_major);
            __syncwarp();
            const int r2 = lane >> 1, cq = lane & 1;
            const int row = m0 + r2;
            const int grow = row0 + row;
            if (grow < N) {
                const int c0 = n0 + cq * 8;
                float4 d0 = *(const float4*)&D[row * LDD2 + c0];
                float4 d1 = *(const float4*)&D[row * LDD2 + c0 + 4];
                float4 o0 = make_float4((d0.x + b2s[c0 + 0]) * sc, (d0.y + b2s[c0 + 1]) * sc,
                                        (d0.z + b2s[c0 + 2]) * sc, (d0.w + b2s[c0 + 3]) * sc);
                float4 o1 = make_float4((d1.x + b2s[c0 + 4]) * sc, (d1.y + b2s[c0 + 5]) * sc,
                                        (d1.z + b2s[c0 + 6]) * sc, (d1.w + b2s[c0 + 7]) * sc);
                *(float4*)&g_L[(size_t)grow * 32 + c0] = o0;
                *(float4*)&g_L[(size_t)grow * 32 + c0 + 4] = o1;
            }
        }
        __syncthreads();
    }
}

// ---------------- persistent Sinkhorn ----------------
__device__ __forceinline__ int eswz(int row, int q) { return (q ^ (row & 7)) << 2; }

__global__ void __launch_bounds__(512, 3)
k_sink(int N, int rpb, unsigned int nb, float NK)
{
    extern __shared__ float smf[];
    float* E = smf;                               // [rpb*32] swizzled
    float* r = smf + (size_t)rpb * 32;            // [rpb]
    float* c = r + ((rpb + 3) & ~3);              // [32]
    float* red = c + 32;                          // [16*33]

    const int tid = threadIdx.x, lane = tid & 31, wid = tid >> 5;
    const int n0 = blockIdx.x * rpb;
    const int cnt = max(0, min(rpb, N - n0));

    // load logits -> swizzled E
    for (int f = tid; f < cnt * 8; f += 512) {
        int row = f >> 3, q = f & 7;
        float4 v = *(const float4*)&g_L[(size_t)(n0 + row) * 32 + (q << 2)];
        *(float4*)&E[row * 32 + eswz(row, q)] = v;
    }
    if (tid < 32) c[tid] = 1.f;
    __syncthreads();

    // E = exp(L - rowmax); publish rowmax directly (coalesced)
    for (int row = tid; row < cnt; row += 512) {
        float* Er = &E[row * 32];
        const int sw = row & 7;
        float e[32];
        float m = -1e30f;
#pragma unroll
        for (int q = 0; q < 8; q++) {
            float4 t = *(const float4*)(Er + ((q ^ sw) << 2));
            e[4*q] = t.x; e[4*q+1] = t.y; e[4*q+2] = t.z; e[4*q+3] = t.w;
            m = fmaxf(m, fmaxf(fmaxf(t.x, t.y), fmaxf(t.z, t.w)));
        }
        g_m[n0 + row] = m;
#pragma unroll
        for (int q = 0; q < 8; q++) {
            float4 t;
            t.x = __expf(e[4*q] - m);   t.y = __expf(e[4*q+1] - m);
            t.z = __expf(e[4*q+2] - m); t.w = __expf(e[4*q+3] - m);
            *(float4*)(Er + ((q ^ sw) << 2)) = t;
        }
    }
    __syncthreads();

    for (int it = 0; it < ITERS; it++) {
        const bool last = (it == ITERS - 1);
        // pass A: r[row] = 1 / sum_k E*c  (last iter: also publish to g_r)
        for (int row = tid; row < cnt; row += 512) {
            const float* Er = &E[row * 32];
            const int sw = row & 7;
            float s = 0.f;
#pragma unroll
            for (int q = 0; q < 8; q++) {
                float4 t = *(const float4*)(Er + ((q ^ sw) << 2));
                float4 cc = *(const float4*)&c[q << 2];
                s = fmaf(t.x, cc.x, s);
                s = fmaf(t.y, cc.y, s);
                s = fmaf(t.z, cc.z, s);
                s = fmaf(t.w, cc.w, s);
            }
            float rr = 1.0f / s;
            r[row] = rr;
            if (last) g_r[n0 + row] = rr;
        }
        __syncthreads();

        // pass B: lane-owns-k column sums
        {
            int cpw = (cnt + 15) >> 4;
            int rs = wid * cpw, re = min(rs + cpw, cnt);
            float tlk = 0.f;
            for (int row = rs; row < re; row++) {
                float ev = E[row * 32 + ((((lane >> 2) ^ (row & 7)) << 2) | (lane & 3))];
                tlk = fmaf(ev, r[row], tlk);
            }
            red[wid * 33 + lane] = tlk;
        }
        __syncthreads();
        if (tid < 32) {
            float s = 0.f;
#pragma unroll
            for (int w = 0; w < 16; w++) s += red[w * 33 + tid];
            atomicAdd(&g_t[it][tid], s);
            __threadfence();
        }
        __syncthreads();
        if (!last) {   // pool reads c19 itself; no final barrier needed for this block
            if (tid == 0) {
                atomicAdd(&g_cnt[it], 1u);
                // volatile read + side effect: prevents hoist AND UB-deletion of the
                // spin (root cause of the R9/R10 silent barrier no-op).
                while (*(volatile const unsigned int*)&g_cnt[it] < nb) { __nanosleep(32); }
            }
            __syncthreads();
            if (tid < 32) c[tid] = NK / __ldcg(&g_t[it][tid]);
            __syncthreads();
        }
    }
}

// ---------------- throughput pooling: out[b] += S^T X, S = exp(L-m)*r*c; 32-row chunks ----------------
__global__ void __launch_bounds__(512)
k_pool(const float* __restrict__ x, const int* __restrict__ batch,
       float* __restrict__ out, int N, int rpp, float NK)
{
    __shared__ __nv_bfloat16 shi[32 * 40], slo[32 * 40];
    __shared__ __nv_bfloat16 xhi[32 * 136], xlo[32 * 136];
    __shared__ float Dp[16 * 132];
    __shared__ float cpool[32];
    __shared__ int bs[32];

    const int tid = threadIdx.x;
    const int wid = tid >> 5;
    const int p0 = blockIdx.x * rpp;
    const int cnt = min(rpp, N - p0);
    if (cnt <= 0) return;

    const int mt = wid & 1;
    const int nt = wid >> 1;
    const int prow = tid >> 5, pq = tid & 31;   // prow 0..15; handles rows prow & prow+16

    if (tid < 32) cpool[tid] = NK / __ldcg(&g_t[ITERS - 1][tid]);

    wmma::fragment<wmma::accumulator, 16, 16, 16, float> pacc;
    wmma::fill_fragment(pacc, 0.f);
    int cur_b = -1;

#define POOL_FLUSH(BB) do { \
    __syncthreads(); \
    if (mt == 0) wmma::store_matrix_sync(&Dp[nt * 16], pacc, 132, wmma::mem_row_major); \
    __syncthreads(); \
    for (int f2 = tid; f2 < 2048; f2 += 512) { \
        int mm = f2 >> 7, cc2 = f2 & 127; \
        atomicAdd(&out[(((BB) * 32 + mm) << 7) + cc2], Dp[mm * 132 + cc2]); \
    } \
    __syncthreads(); \
    if (mt == 1) wmma::store_matrix_sync(&Dp[nt * 16], pacc, 132, wmma::mem_row_major); \
    __syncthreads(); \
    for (int f2 = tid; f2 < 2048; f2 += 512) { \
        int mm = f2 >> 7, cc2 = f2 & 127; \
        atomicAdd(&out[(((BB) * 32 + 16 + mm) << 7) + cc2], Dp[mm * 132 + cc2]); \
    } \
    wmma::fill_fragment(pacc, 0.f); \
} while (0)

    // prefetch chunk 0 (2 rows per thread)
    float4 xreg[2];
    float lreg[2], rreg[2], mreg[2];
    int breg[2];
#pragma unroll
    for (int j = 0; j < 2; j++) {
        xreg[j] = make_float4(0.f, 0.f, 0.f, 0.f);
        lreg[j] = rreg[j] = mreg[j] = 0.f;
        breg[j] = -1;
        int row = prow + j * 16;
        if (row < cnt) {
            xreg[j] = ((const float4*)x)[(size_t)(p0 + row) * 32 + pq];
            lreg[j] = g_L[(size_t)(p0 + row) * 32 + pq];
            rreg[j] = g_r[p0 + row];
            mreg[j] = g_m[p0 + row];
            if (pq == 0) breg[j] = batch[p0 + row];
        }
    }

    for (int s0 = 0; s0 < cnt; s0 += 32) {
        const int nr = min(32, cnt - s0);
        __syncthreads();
        float scur[2];
#pragma unroll
        for (int j = 0; j < 2; j++) {
            int row = prow + j * 16;
            scur[j] = (row < nr) ? __expf(lreg[j] - mreg[j]) * rreg[j] * cpool[pq] : 0.f;
            uint2 hi = make_uint2(0u, 0u), lo = make_uint2(0u, 0u);
            if (row < nr) split4(xreg[j].x, xreg[j].y, xreg[j].z, xreg[j].w, hi, lo);
            *(uint2*)&xhi[row * 136 + pq * 4] = hi;
            *(uint2*)&xlo[row * 136 + pq * 4] = lo;
            __nv_bfloat16 h = __float2bfloat16(scur[j]);
            shi[row * 40 + pq] = h;
            slo[row * 40 + pq] = __float2bfloat16(scur[j] - __bfloat162float(h));
            if (pq == 0) bs[row] = (row < nr) ? breg[j] : -1;
        }
        // prefetch next chunk
#pragma unroll
        for (int j = 0; j < 2; j++) {
            int np = s0 + 32 + prow + j * 16;
            if (np < cnt) {
                xreg[j] = ((const float4*)x)[(size_t)(p0 + np) * 32 + pq];
                lreg[j] = g_L[(size_t)(p0 + np) * 32 + pq];
                rreg[j] = g_r[p0 + np];
                mreg[j] = g_m[p0 + np];
                if (pq == 0) breg[j] = batch[p0 + np];
            }
        }
        __syncthreads();

        int pos = 0;
        while (pos < nr) {
            int seg = bs[pos];
            int e = pos + 1;
            while (e < nr && bs[e] == seg) e++;
            if (seg != cur_b) {
                if (cur_b >= 0) POOL_FLUSH(cur_b);
                cur_b = seg;
            }
            bool full = (pos == 0 && e == nr);
            if (!full) {  // rare: rebuild masked S for both row groups
                __syncthreads();
#pragma unroll
                for (int j = 0; j < 2; j++) {
                    int row = prow + j * 16;
                    float sv = (row >= pos && row < e) ? scur[j] : 0.f;
                    __nv_bfloat16 h = __float2bfloat16(sv);
                    shi[row * 40 + pq] = h;
                    slo[row * 40 + pq] = __float2bfloat16(sv - __bfloat162float(h));
                }
                __syncthreads();
            }
#pragma unroll
            for (int kc = 0; kc < 2; kc++) {
                wmma::fragment<wmma::matrix_a, 16, 16, 16, __nv_bfloat16, wmma::col_major> sa_h, sa_l;
                wmma::fragment<wmma::matrix_b, 16, 16, 16, __nv_bfloat16, wmma::row_major> xb_h, xb_l;
                wmma::load_matrix_sync(sa_h, &shi[kc * 16 * 40 + mt * 16], 40);
                wmma::load_matrix_sync(sa_l, &slo[kc * 16 * 40 + mt * 16], 40);
                wmma::load_matrix_sync(xb_h, &xhi[kc * 16 * 136 + nt * 16], 136);
                wmma::load_matrix_sync(xb_l, &xlo[kc * 16 * 136 + nt * 16], 136);
                wmma::mma_sync(pacc, sa_h, xb_h, pacc);
                wmma::mma_sync(pacc, sa_h, xb_l, pacc);
                wmma::mma_sync(pacc, sa_l, xb_h, pacc);
            }
            pos = e;
        }
    }
    if (cur_b >= 0) POOL_FLUSH(cur_b);
#undef POOL_FLUSH
}

// ---------------- launch ----------------
extern "C" void kernel_launch(void* const* d_in, const int* in_sizes, int n_in,
                              void* d_out, int out_size)
{
    const float* x       = (const float*)d_in[0];
    const int*   batch   = (const int*)d_in[1];
    const float* W1      = (const float*)d_in[2];
    const float* b1      = (const float*)d_in[3];
    const float* W2      = (const float*)d_in[4];
    const float* b2      = (const float*)d_in[5];
    const float* scaling = (const float*)d_in[6];

    const int N = in_sizes[0] / C_DIM;

    int dev = 0, nsm = 148;
    cudaGetDevice(&dev);
    cudaDeviceGetAttribute(&nsm, cudaDevAttrMultiProcessorCount, dev);

    const int ntiles = (N + 127) >> 7;
    const int gl = ntiles < nsm ? ntiles : nsm;

    // sink smem: E rpb*32 + r (padded) + c 32 + red 528 + pad
    auto sink_smem = [](int rpb) -> size_t {
        return ((size_t)rpb * 32 + (size_t)((rpb + 3) & ~3) + 32 + 528 + 16) * 4;
    };
    const int nb3 = nsm * 3, nb2 = nsm * 2, nb1 = nsm;
    const int rpb3 = (N + nb3 - 1) / nb3;
    const int rpb2 = (N + nb2 - 1) / nb2;
    const int rpb1 = (N + nb1 - 1) / nb1;
    const size_t sm3 = sink_smem(rpb3), sm2 = sink_smem(rpb2), sm1 = sink_smem(rpb1);

    cudaFuncSetAttribute(k_logits_tc, cudaFuncAttributeMaxDynamicSharedMemorySize, SMEM_TC);
    cudaFuncSetAttribute(k_sink, cudaFuncAttributeMaxDynamicSharedMemorySize, (int)sm1);

    int o3 = 0, o2 = 0;
    cudaOccupancyMaxActiveBlocksPerMultiprocessor(&o3, k_sink, 512, sm3);
    cudaOccupancyMaxActiveBlocksPerMultiprocessor(&o2, k_sink, 512, sm2);

    int nb, rpb; size_t sms;
    if (o3 >= 3)      { nb = nb3; rpb = rpb3; sms = sm3; }
    else if (o2 >= 2) { nb = nb2; rpb = rpb2; sms = sm2; }
    else              { nb = nb1; rpb = rpb1; sms = sm1; }

    // pool rows-per-block multiple of 32
    int rpp = ((N + nsm * 4 - 1) / (nsm * 4) + 31) & ~31;
    int G = (N + rpp - 1) / rpp;

    void* gt_addr = nullptr; void* gc_addr = nullptr;
    cudaGetSymbolAddress(&gt_addr, g_t);
    cudaGetSymbolAddress(&gc_addr, g_cnt);
    cudaMemsetAsync(gt_addr, 0, sizeof(float) * ITERS * K_DIM);
    cudaMemsetAsync(gc_addr, 0, sizeof(unsigned int) * ITERS);
    cudaMemsetAsync(d_out, 0, (size_t)out_size * sizeof(float));

    k_logits_tc<<<gl, 512, SMEM_TC>>>(x, W1, b1, W2, b2, scaling, N, ntiles);

    const float NK = (float)N / (float)K_DIM + 1e-9f;
    k_sink<<<nb, 512, sms>>>(N, rpb, (unsigned)nb, NK);
    k_pool<<<G, 512, 0>>>(x, batch, (float*)d_out, N, rpp, NK);
}